// round 11
// baseline (speedup 1.0000x reference)
#include <cuda_runtime.h>
#include <cstdint>

#define N_UNITS   400
#define N_NEIGHB  64
#define N_CELLS   (N_UNITS * N_NEIGHB)   // 25600
#define BLK       256

// Scratch (no device allocation allowed)
__device__ int g_counts[N_CELLS];
__device__ int g_explore[N_NEIGHB * N_UNITS];
__device__ int g_nexplore[N_NEIGHB];

// ---------------------------------------------------------------------------
// JAX threefry2x32-20, partitionable path, key = jax.random.key(1) -> (0, 1).
// bits[i] = b1 ^ b2 with (b1,b2) = threefry2x32((0,1), (hi32(i)=0, lo32(i)=i))
// uniform = bitcast((bits >> 9) | 0x3f800000) - 1.0f   (max(0,.) is identity)
// ---------------------------------------------------------------------------
__device__ __forceinline__ float tf_uniform(unsigned i) {
    const unsigned k0 = 0u;
    const unsigned k1 = 1u;
    const unsigned k2 = 0x1BD11BDAu ^ k0 ^ k1;   // 0x1BD11BDB

    unsigned x0 = 0u + k0;   // hi32(iota) = 0
    unsigned x1 = i + k1;

#define TF_ROUND(r) { x0 += x1; x1 = __funnelshift_l(x1, x1, (r)); x1 ^= x0; }

    TF_ROUND(13) TF_ROUND(15) TF_ROUND(26) TF_ROUND(6)
    x0 += k1; x1 += k2 + 1u;
    TF_ROUND(17) TF_ROUND(29) TF_ROUND(16) TF_ROUND(24)
    x0 += k2; x1 += k0 + 2u;
    TF_ROUND(13) TF_ROUND(15) TF_ROUND(26) TF_ROUND(6)
    x0 += k0; x1 += k1 + 3u;
    TF_ROUND(17) TF_ROUND(29) TF_ROUND(16) TF_ROUND(24)
    x0 += k1; x1 += k2 + 4u;
    TF_ROUND(13) TF_ROUND(15) TF_ROUND(26) TF_ROUND(6)
    x0 += k2; x1 += k0 + 5u;

#undef TF_ROUND

    unsigned bits = x0 ^ x1;
    return __uint_as_float((bits >> 9) | 0x3f800000u) - 1.0f;
}

// ---------------------------------------------------------------------------
__global__ void zero_counts_kernel() {
    int i = blockIdx.x * blockDim.x + threadIdx.x;
    if (i < N_CELLS) g_counts[i] = 0;
}

__global__ void phase1_kernel(const int* __restrict__ top,
                              const int* __restrict__ nbid, int n) {
    int i = blockIdx.x * blockDim.x + threadIdx.x;
    if (i < n) {
        int u  = top[i * 3];
        int nb = nbid[i];
        atomicAdd(&g_counts[u * N_NEIGHB + nb], 1);
    }
}

// One block per neighborhood; thread u tests counts[u, nb] > 0, block-wide
// prefix sum gives the sorted (ascending u) explore list.
__global__ void build_explore_kernel() {
    __shared__ int warp_sums[13];
    int nb = blockIdx.x;
    int u  = threadIdx.x;          // blockDim = 416 = 13 warps
    int lane = u & 31;
    int wid  = u >> 5;

    int flag = 0;
    if (u < N_UNITS) flag = (g_counts[u * N_NEIGHB + nb] > 0) ? 1 : 0;

    unsigned ballot = __ballot_sync(0xffffffffu, flag);
    int prefix = __popc(ballot & ((1u << lane) - 1u));
    if (lane == 0) warp_sums[wid] = __popc(ballot);
    __syncthreads();

    int base = 0;
#pragma unroll
    for (int w = 0; w < 13; w++)
        if (w < wid) base += warp_sums[w];

    if (flag) g_explore[nb * N_UNITS + base + prefix] = u;

    if (u == 0) {
        int tot = 0;
#pragma unroll
        for (int w = 0; w < 13; w++) tot += warp_sums[w];
        g_nexplore[nb] = tot;
    }
}

// ---------------------------------------------------------------------------
// Main per-spike kernel: build candidates, counts tail update, dedup, scores.
// Stores go through shared-memory staging so global writes are fully coalesced.
// ---------------------------------------------------------------------------
__global__ __launch_bounds__(BLK)
void phase3_kernel(const float* __restrict__ logliks,
                   const int*   __restrict__ top,
                   const int*   __restrict__ usn,
                   const int*   __restrict__ nbid,
                   float*       __restrict__ out,
                   int n) {
    __shared__ int   s_usn[N_UNITS * 2];
    __shared__ float s_ll[N_UNITS];
    __shared__ int   s_ne[N_NEIGHB];
    __shared__ int   s_top[BLK * 3];
    __shared__ float s_stage[BLK * 10];

    const int t    = threadIdx.x;
    const int base = blockIdx.x * BLK;

    for (int k = t; k < N_UNITS * 2; k += BLK) s_usn[k] = usn[k];
    for (int k = t; k < N_UNITS;     k += BLK) s_ll[k]  = logliks[k];
    if (t < N_NEIGHB) s_ne[t] = g_nexplore[t];

    const int ntop = n * 3;
    for (int k = t; k < BLK * 3; k += BLK) {
        int g = base * 3 + k;
        s_top[k] = (g < ntop) ? top[g] : 0;
    }
    __syncthreads();

    const int  i      = base + t;
    const bool active = (i < n);

    int   o[10];
    float sc[10];

    if (active) {
        int c[10];
        c[0] = s_top[t * 3 + 0];
        c[1] = s_top[t * 3 + 1];
        c[2] = s_top[t * 3 + 2];
        int nb = nbid[i];

        c[3] = s_usn[2 * c[0]];     c[4] = s_usn[2 * c[0] + 1];
        c[5] = s_usn[2 * c[1]];     c[6] = s_usn[2 * c[1] + 1];
        c[7] = s_usn[2 * c[2]];     c[8] = s_usn[2 * c[2] + 1];

        int ne = s_ne[nb];
        float u = tf_uniform((unsigned)i);
        if (ne > 0) {
            int targ = __float2int_rd(u * (float)ne);   // floor(u * ne)
            targ = min(targ, ne - 1);
            c[9] = g_explore[nb * N_UNITS + targ];
        } else {
            c[9] = -1;
        }

        // counts tail update (pre-dedup candidates, columns 1..9)
#pragma unroll
        for (int j = 1; j < 9; j++)
            atomicAdd(&g_counts[c[j] * N_NEIGHB + nb], 1);
        if (c[9] >= 0)
            atomicAdd(&g_counts[c[9] * N_NEIGHB + nb], 1);

        // dedup against ORIGINAL values (all marks simultaneous)
        o[0] = c[0];
#pragma unroll
        for (int j = 1; j < 10; j++) {
            bool dup = false;
#pragma unroll
            for (int k = 0; k < 10; k++)
                if (k < j) dup |= (c[j] == c[k]);
            o[j] = dup ? -1 : c[j];
        }

#pragma unroll
        for (int j = 0; j < 10; j++)
            sc[j] = (o[j] >= 0) ? s_ll[o[j]] : 0.0f;
    }

    // ---- coalesced flush: candidates ----
    __syncthreads();
    if (active) {
#pragma unroll
        for (int j = 0; j < 10; j++) s_stage[t * 10 + j] = (float)o[j];
    }
    __syncthreads();
    {
        int rows  = n - base; if (rows > BLK) rows = BLK;
        int total = rows * 10;
        float* dst = out + (size_t)base * 10;
        for (int k = t; k < total; k += BLK) dst[k] = s_stage[k];
    }

    // ---- coalesced flush: scores ----
    __syncthreads();
    if (active) {
#pragma unroll
        for (int j = 0; j < 10; j++) s_stage[t * 10 + j] = sc[j];
    }
    __syncthreads();
    {
        int rows  = n - base; if (rows > BLK) rows = BLK;
        int total = rows * 10;
        float* dst = out + (size_t)n * 10 + (size_t)N_CELLS + (size_t)base * 10;
        for (int k = t; k < total; k += BLK) dst[k] = s_stage[k];
    }
}

__global__ void counts_out_kernel(float* __restrict__ dst) {
    int i = blockIdx.x * blockDim.x + threadIdx.x;
    if (i < N_CELLS) dst[i] = (float)g_counts[i];
}

// ---------------------------------------------------------------------------
extern "C" void kernel_launch(void* const* d_in, const int* in_sizes, int n_in,
                              void* d_out, int out_size) {
    const float* logliks = (const float*)d_in[0];   // (400,) f32
    const int*   top     = (const int*)  d_in[1];   // (n, 3) i32
    const int*   usn     = (const int*)  d_in[2];   // (400, 2) i32
    const int*   nbid    = (const int*)  d_in[3];   // (n,) i32
    float*       out     = (float*)d_out;

    const int n = in_sizes[3];

    zero_counts_kernel<<<(N_CELLS + BLK - 1) / BLK, BLK>>>();
    phase1_kernel<<<(n + BLK - 1) / BLK, BLK>>>(top, nbid, n);
    build_explore_kernel<<<N_NEIGHB, 416>>>();
    phase3_kernel<<<(n + BLK - 1) / BLK, BLK>>>(logliks, top, usn, nbid, out, n);
    counts_out_kernel<<<(N_CELLS + BLK - 1) / BLK, BLK>>>(out + (size_t)n * 10);
}

// round 12
// speedup vs baseline: 2.5907x; 2.5907x over previous
#include <cuda_runtime.h>
#include <cstdint>

#define N_UNITS   400
#define N_NEIGHB  64
#define N_CELLS   (N_UNITS * N_NEIGHB)   // 25600
#define BLK       256

// Scratch (no device allocation allowed). Layout: cell = nb * N_UNITS + u.
__device__ int   g_counts[N_CELLS];                 // phase1: cnt(c0); phase3 adds c1,c2 -> cnt_all
__device__ int   g_ex[N_CELLS];                     // explore counts, then final counts after fixup
__device__ short g_explore[N_NEIGHB * N_UNITS];     // sorted overlapping units per neighborhood
__device__ int   g_nexplore[N_NEIGHB];

// ---------------------------------------------------------------------------
// JAX threefry2x32-20, partitionable path, key = jax.random.key(1) -> (0, 1).
// bits[i] = x0 ^ x1 after 20 rounds on (0, i); uniform = bitcast((bits>>9)|0x3f800000)-1
// (verified bit-exact: rel_err == 0.0 in round 11)
// ---------------------------------------------------------------------------
__device__ __forceinline__ float tf_uniform(unsigned i) {
    const unsigned k0 = 0u;
    const unsigned k1 = 1u;
    const unsigned k2 = 0x1BD11BDAu ^ k0 ^ k1;   // 0x1BD11BDB

    unsigned x0 = 0u + k0;
    unsigned x1 = i + k1;

#define TF_ROUND(r) { x0 += x1; x1 = __funnelshift_l(x1, x1, (r)); x1 ^= x0; }

    TF_ROUND(13) TF_ROUND(15) TF_ROUND(26) TF_ROUND(6)
    x0 += k1; x1 += k2 + 1u;
    TF_ROUND(17) TF_ROUND(29) TF_ROUND(16) TF_ROUND(24)
    x0 += k2; x1 += k0 + 2u;
    TF_ROUND(13) TF_ROUND(15) TF_ROUND(26) TF_ROUND(6)
    x0 += k0; x1 += k1 + 3u;
    TF_ROUND(17) TF_ROUND(29) TF_ROUND(16) TF_ROUND(24)
    x0 += k1; x1 += k2 + 4u;
    TF_ROUND(13) TF_ROUND(15) TF_ROUND(26) TF_ROUND(6)
    x0 += k2; x1 += k0 + 5u;

#undef TF_ROUND

    unsigned bits = x0 ^ x1;
    return __uint_as_float((bits >> 9) | 0x3f800000u) - 1.0f;
}

// ---------------------------------------------------------------------------
__global__ void zero_counts_kernel() {
    int i = blockIdx.x * blockDim.x + threadIdx.x;
    if (i < N_CELLS) { g_counts[i] = 0; g_ex[i] = 0; }
}

__global__ void phase1_kernel(const int* __restrict__ top,
                              const int* __restrict__ nbid, int n) {
    int i = blockIdx.x * blockDim.x + threadIdx.x;
    if (i < n) {
        int u  = top[i * 3];
        int nb = nbid[i];
        atomicAdd(&g_counts[nb * N_UNITS + u], 1);
    }
}

// One block per neighborhood; coalesced read of g_counts[nb*400 + u].
__global__ void build_explore_kernel() {
    __shared__ int warp_sums[13];
    int nb   = blockIdx.x;
    int u    = threadIdx.x;        // blockDim = 416 = 13 warps
    int lane = u & 31;
    int wid  = u >> 5;

    int flag = 0;
    if (u < N_UNITS) flag = (g_counts[nb * N_UNITS + u] > 0) ? 1 : 0;

    unsigned ballot = __ballot_sync(0xffffffffu, flag);
    int prefix = __popc(ballot & ((1u << lane) - 1u));
    if (lane == 0) warp_sums[wid] = __popc(ballot);
    __syncthreads();

    int base = 0;
#pragma unroll
    for (int w = 0; w < 13; w++)
        if (w < wid) base += warp_sums[w];

    if (flag) g_explore[nb * N_UNITS + base + prefix] = (short)u;

    if (u == 0) {
        int tot = 0;
#pragma unroll
        for (int w = 0; w < 13; w++) tot += warp_sums[w];
        g_nexplore[nb] = tot;
    }
}

// ---------------------------------------------------------------------------
// Main per-spike kernel. 3 atomics/spike (c1, c2, explore); vectorized staging.
// ---------------------------------------------------------------------------
__global__ __launch_bounds__(BLK)
void phase3_kernel(const float* __restrict__ logliks,
                   const int*   __restrict__ top,
                   const int*   __restrict__ usn,
                   const int*   __restrict__ nbid,
                   float*       __restrict__ out,
                   int n) {
    __shared__ int   s_usn[N_UNITS * 2];
    __shared__ float s_ll[N_UNITS];
    __shared__ int   s_ne[N_NEIGHB];
    __shared__ int   s_top[BLK * 3];
    __shared__ float s_cand[BLK * 10];
    __shared__ float s_sc[BLK * 10];

    const int t    = threadIdx.x;
    const int base = blockIdx.x * BLK;

    // vectorized preloads
    if (t < N_UNITS * 2 / 4) ((int4*)s_usn)[t] = ((const int4*)usn)[t];
    if (t < N_UNITS / 4)     ((float4*)s_ll)[t] = ((const float4*)logliks)[t];
    if (t >= BLK - N_NEIGHB) s_ne[t - (BLK - N_NEIGHB)] = g_nexplore[t - (BLK - N_NEIGHB)];

    if (base + BLK <= n) {
        // full block: 768 ints = 192 int4
        if (t < 192) ((int4*)s_top)[t] = ((const int4*)(top + (size_t)base * 3))[t];
    } else {
        const int ntop = n * 3;
        for (int k = t; k < BLK * 3; k += BLK) {
            int g = base * 3 + k;
            s_top[k] = (g < ntop) ? top[g] : 0;
        }
    }
    __syncthreads();

    const int  i      = base + t;
    const bool active = (i < n);

    if (active) {
        int c[10];
        c[0] = s_top[t * 3 + 0];
        c[1] = s_top[t * 3 + 1];
        c[2] = s_top[t * 3 + 2];
        int nb = nbid[i];

        c[3] = s_usn[2 * c[0]];     c[4] = s_usn[2 * c[0] + 1];
        c[5] = s_usn[2 * c[1]];     c[6] = s_usn[2 * c[1] + 1];
        c[7] = s_usn[2 * c[2]];     c[8] = s_usn[2 * c[2] + 1];

        int ne = s_ne[nb];
        float u = tf_uniform((unsigned)i);
        if (ne > 0) {
            int targ = __float2int_rd(u * (float)ne);
            targ = min(targ, ne - 1);
            c[9] = (int)g_explore[nb * N_UNITS + targ];
        } else {
            c[9] = -1;
        }

        // counts: only c1, c2 here (search neighbors reconstructed in fixup)
        atomicAdd(&g_counts[nb * N_UNITS + c[1]], 1);
        atomicAdd(&g_counts[nb * N_UNITS + c[2]], 1);
        if (c[9] >= 0)
            atomicAdd(&g_ex[nb * N_UNITS + c[9]], 1);

        // in-place dedup (marking dup -> -1 is semantics-preserving: a later
        // value equal to an overwritten dup also equals the original earlier one,
        // and -1 collisions only collapse -1 to -1)
#pragma unroll
        for (int j = 1; j < 10; j++) {
            bool dup = false;
#pragma unroll
            for (int k = 0; k < 10; k++)
                if (k < j) dup |= (c[j] == c[k]);
            if (dup) c[j] = -1;
        }

#pragma unroll
        for (int j = 0; j < 10; j++) {
            int v = c[j];
            s_cand[t * 10 + j] = (float)v;
            s_sc[t * 10 + j]   = (v >= 0) ? s_ll[v] : 0.0f;
        }
    }
    __syncthreads();

    // coalesced vectorized flush of both staged arrays
    {
        int rows  = n - base; if (rows > BLK) rows = BLK;
        int total = rows * 10;

        float* dstc = out + (size_t)base * 10;
        float* dsts = out + (size_t)n * 10 + (size_t)N_CELLS + (size_t)base * 10;

        bool al = ((((uintptr_t)dstc) | ((uintptr_t)dsts)) & 15u) == 0 && (total & 3) == 0;
        if (al) {
            int total4 = total >> 2;
            const float4* sc4 = (const float4*)s_cand;
            const float4* ss4 = (const float4*)s_sc;
            float4* dc4 = (float4*)dstc;
            float4* ds4 = (float4*)dsts;
            for (int k = t; k < total4; k += BLK) { dc4[k] = sc4[k]; ds4[k] = ss4[k]; }
        } else {
            for (int k = t; k < total; k += BLK) { dstc[k] = s_cand[k]; dsts[k] = s_sc[k]; }
        }
    }
}

// Expand search-neighbor contributions: for each (nb,u) with a = cnt_all[u,nb],
// final += a at (u,nb), (usn[u,0],nb), (usn[u,1],nb). g_ex already holds explore counts.
__global__ void fixup_kernel(const int* __restrict__ usn) {
    int i = blockIdx.x * blockDim.x + threadIdx.x;
    if (i < N_CELLS) {
        int a = g_counts[i];
        if (a) {
            int nb = i / N_UNITS;
            int u  = i - nb * N_UNITS;
            atomicAdd(&g_ex[i], a);
            atomicAdd(&g_ex[nb * N_UNITS + usn[2 * u]], a);
            atomicAdd(&g_ex[nb * N_UNITS + usn[2 * u + 1]], a);
        }
    }
}

// out layout wants counts[u, nb]; scratch is [nb, u] -> transpose on write.
__global__ void counts_out_kernel(float* __restrict__ dst) {
    int j = blockIdx.x * blockDim.x + threadIdx.x;   // j = u*64 + nb
    if (j < N_CELLS) {
        int u  = j >> 6;
        int nb = j & 63;
        dst[j] = (float)g_ex[nb * N_UNITS + u];
    }
}

// ---------------------------------------------------------------------------
extern "C" void kernel_launch(void* const* d_in, const int* in_sizes, int n_in,
                              void* d_out, int out_size) {
    const float* logliks = (const float*)d_in[0];   // (400,) f32
    const int*   top     = (const int*)  d_in[1];   // (n, 3) i32
    const int*   usn     = (const int*)  d_in[2];   // (400, 2) i32
    const int*   nbid    = (const int*)  d_in[3];   // (n,) i32
    float*       out     = (float*)d_out;

    const int n = in_sizes[3];

    zero_counts_kernel<<<(N_CELLS + BLK - 1) / BLK, BLK>>>();
    phase1_kernel<<<(n + BLK - 1) / BLK, BLK>>>(top, nbid, n);
    build_explore_kernel<<<N_NEIGHB, 416>>>();
    phase3_kernel<<<(n + BLK - 1) / BLK, BLK>>>(logliks, top, usn, nbid, out, n);
    fixup_kernel<<<(N_CELLS + BLK - 1) / BLK, BLK>>>(usn);
    counts_out_kernel<<<(N_CELLS + BLK - 1) / BLK, BLK>>>(out + (size_t)n * 10);
}